// round 12
// baseline (speedup 1.0000x reference)
#include <cuda_runtime.h>

// B=2, C=4, D=64, H=256, W=256; channels 1..3 of pred/trgt.
// scale(10)/(2*DELTA=10) cancels; vorticity linear -> stencil on (pred-trgt).
// keep voxel <=> min over 3^3 mask neighborhood == 1 (center included).
//
// R12: R11 + L2 prefetch of all stencil taps issued BEFORE the mask epoch.
// Registers cap in-flight LDG bytes (~3 TB/s plateau across R6/R9/R11);
// prefetch.global.L2 carries no register/dependency cost, so the stencil
// lines stream into L2 during the mask latency and the demand loads hit L2.

constexpr int DN = 64, HN = 256, WN = 256;
constexpr long sD = (long)HN * WN;          // 65536
constexpr long sH = WN;                     // 256
constexpr long CS = (long)DN * HN * WN;     // 4194304
constexpr int HT = 4;                       // h rows per block
constexpr int NHX = 64;                     // ceil(254/4)
constexpr int NPART = NHX * 62 * 2;         // 7936 blocks

__device__ float2 g_part[NPART];
__device__ int g_counter;                   // zero-init; self-resets each launch

__device__ __forceinline__ float4 ld4(const float* p) {
    return __ldg(reinterpret_cast<const float4*>(p));
}
__device__ __forceinline__ float4 min4(float4 a, float4 b) {
    return make_float4(fminf(a.x,b.x), fminf(a.y,b.y), fminf(a.z,b.z), fminf(a.w,b.w));
}
__device__ __forceinline__ float4 sub4(float4 a, float4 b) {
    return make_float4(a.x-b.x, a.y-b.y, a.z-b.z, a.w-b.w);
}
// (p[+off]-t[+off]) - (p[-off]-t[-off])
__device__ __forceinline__ float4 dd4(const float* p, const float* t, long off) {
    return sub4(sub4(ld4(p + off), ld4(t + off)), sub4(ld4(p - off), ld4(t - off)));
}
__device__ __forceinline__ void pf(const float* p) {
    asm volatile("prefetch.global.L2 [%0];" :: "l"(p));
}

// Grid: (NHX, 62, 2)  block: 256 = 4 h-rows x 64 w-threads (float4 each).
__global__ __launch_bounds__(256) void vort_kernel(
    const float* __restrict__ pred,
    const float* __restrict__ trgt,
    const float* __restrict__ mask,
    float* __restrict__ out)
{
    const int tid  = threadIdx.x;
    const int row  = tid >> 6;               // 0..3
    const int t    = tid & 63;               // w-group
    const int lane = tid & 31;
    const int w4   = t << 2;                 // first w of this thread
    const int h    = 1 + blockIdx.x * HT + row;
    const int hc   = min(h, HN - 2);         // clamp; h>254 discarded later
    const int d    = 1 + blockIdx.y;         // 1..62
    const int b    = blockIdx.z;

    // channel base pointers (used by prefetch now, loads later)
    const long pb = (long)b * 4 * CS + (long)d * sD + (long)hc * sH + w4;
    const float* pu = pred + pb + 1 * CS;
    const float* pv = pred + pb + 2 * CS;
    const float* pw = pred + pb + 3 * CS;
    const float* tu = trgt + pb + 1 * CS;
    const float* tv = trgt + pb + 2 * CS;
    const float* tw = trgt + pb + 3 * CS;

    // ---- fire-and-forget L2 prefetch of every stencil tap (no reg cost) ----
    pf(pu + sD); pf(pu - sD); pf(tu + sD); pf(tu - sD);     // du/dD
    pf(pu + sH); pf(pu - sH); pf(tu + sH); pf(tu - sH);     // du/dH
    pf(pv + sD); pf(pv - sD); pf(tv + sD); pf(tv - sD);     // dv/dD
    pf(pv);      pf(tv);                                     // dv/dW (center row)
    pf(pw + sH); pf(pw - sH); pf(tw + sH); pf(tw - sH);     // dw/dH
    pf(pw);      pf(tw);                                     // dw/dW (center row)

    // ---- mask: per-w min over 3x3 (dz,dy) at this thread's 4 w ----
    const float* mb = mask + (long)b * DN * sD + (long)d * sD + (long)hc * sH + w4;
    float4 cm = make_float4(1e9f, 1e9f, 1e9f, 1e9f);
    #pragma unroll
    for (int dz = -1; dz <= 1; dz++)
        #pragma unroll
        for (int dy = -1; dy <= 1; dy++)
            cm = min4(cm, ld4(mb + (long)dz * sD + (long)dy * sH));

    __shared__ float cs[HT][WN];
    *reinterpret_cast<float4*>(&cs[row][w4]) = cm;
    __syncthreads();

    // w-direction min for keep flags
    const float cmL = cs[row][max(w4 - 1, 0)];
    const float cmR = cs[row][min(w4 + 4, WN - 1)];
    const bool hok = (h <= HN - 2);
    const bool k0 = hok && (w4 > 0)      && fminf(cmL,  fminf(cm.x, cm.y)) > 0.5f;
    const bool k1 = hok &&                  fminf(cm.x, fminf(cm.y, cm.z)) > 0.5f;
    const bool k2 = hok &&                  fminf(cm.y, fminf(cm.z, cm.w)) > 0.5f;
    const bool k3 = hok && (w4 < WN - 4) && fminf(cm.z, fminf(cm.w, cmR)) > 0.5f;

    float numer = 0.0f;
    float den   = 0.0f;

    if (k0 | k1 | k2 | k3) {
        // ---- stencil on (pred - trgt); taps now resident in L2 ----
        float4 du_d = dd4(pu, tu, sD);       // du/dD
        float4 du_h = dd4(pu, tu, sH);       // du/dH
        float4 dv_d = dd4(pv, tv, sD);       // dv/dD
        float4 dw_h = dd4(pw, tw, sH);       // dw/dH
        float4 vc   = sub4(ld4(pv), ld4(tv));
        float4 wc   = sub4(ld4(pw), ld4(tw));

        const long eL = (w4 > 0)      ? -1 : 0;   // clamped; comp discarded at edge
        const long eR = (w4 < WN - 4) ?  4 : 3;
        float vL = __ldg(pv + eL) - __ldg(tv + eL);
        float vR = __ldg(pv + eR) - __ldg(tv + eR);
        float wL = __ldg(pw + eL) - __ldg(tw + eL);
        float wR = __ldg(pw + eR) - __ldg(tw + eR);

        float4 dv_w = make_float4(vc.y - vL, vc.z - vc.x, vc.w - vc.y, vR - vc.z);
        float4 dw_w = make_float4(wc.y - wL, wc.z - wc.x, wc.w - wc.y, wR - wc.z);

        // vor_x = dw/dH - dv/dD ; vor_y = du/dD - dw/dW ; vor_z = dv/dW - du/dH
        float4 vx = sub4(dw_h, dv_d);
        float4 vy = sub4(du_d, dw_w);
        float4 vz = sub4(dv_w, du_h);

        if (k0) { numer += sqrtf(vx.x*vx.x + vy.x*vy.x + vz.x*vz.x); den += 1.0f; }
        if (k1) { numer += sqrtf(vx.y*vx.y + vy.y*vy.y + vz.y*vz.y); den += 1.0f; }
        if (k2) { numer += sqrtf(vx.z*vx.z + vy.z*vy.z + vz.z*vz.z); den += 1.0f; }
        if (k3) { numer += sqrtf(vx.w*vx.w + vy.w*vy.w + vz.w*vz.w); den += 1.0f; }
    }

    // ---- block reduction (8 warps) ----
    #pragma unroll
    for (int s = 16; s; s >>= 1) {
        numer += __shfl_down_sync(0xffffffffu, numer, s);
        den   += __shfl_down_sync(0xffffffffu, den,   s);
    }
    __shared__ float wn[8], wd[8];
    const int wid = tid >> 5;
    if (lane == 0) { wn[wid] = numer; wd[wid] = den; }
    __syncthreads();

    __shared__ bool isLast;
    if (wid == 0) {
        float n2 = (lane < 8) ? wn[lane] : 0.0f;
        float d2 = (lane < 8) ? wd[lane] : 0.0f;
        #pragma unroll
        for (int s = 4; s; s >>= 1) {
            n2 += __shfl_down_sync(0xffffffffu, n2, s);
            d2 += __shfl_down_sync(0xffffffffu, d2, s);
        }
        if (lane == 0) {
            const int bid = blockIdx.x + NHX * (blockIdx.y + 62 * blockIdx.z);
            g_part[bid] = make_float2(n2, d2);
            __threadfence();
            int prev = atomicAdd(&g_counter, 1);
            isLast = (prev == NPART - 1);
        }
    }
    __syncthreads();

    // ---- last block finalizes (no tail kernel) ----
    if (isLast) {
        __threadfence();
        double n = 0.0, dd = 0.0;
        for (int i = tid; i < NPART; i += 256) {
            float2 p = g_part[i];
            n  += (double)p.x;
            dd += (double)p.y;
        }
        #pragma unroll
        for (int s = 16; s; s >>= 1) {
            n  += __shfl_down_sync(0xffffffffu, n,  s);
            dd += __shfl_down_sync(0xffffffffu, dd, s);
        }
        __shared__ double sn[8], sd[8];
        if (lane == 0) { sn[wid] = n; sd[wid] = dd; }
        __syncthreads();
        if (wid == 0) {
            n  = (lane < 8) ? sn[lane] : 0.0;
            dd = (lane < 8) ? sd[lane] : 0.0;
            #pragma unroll
            for (int s = 4; s; s >>= 1) {
                n  += __shfl_down_sync(0xffffffffu, n,  s);
                dd += __shfl_down_sync(0xffffffffu, dd, s);
            }
            if (lane == 0) {
                out[0] = (float)(n / dd);
                g_counter = 0;              // reset for next graph replay
            }
        }
    }
}

extern "C" void kernel_launch(void* const* d_in, const int* in_sizes, int n_in,
                              void* d_out, int out_size) {
    const float* pred = (const float*)d_in[0];   // predicts (2,4,64,256,256)
    const float* trgt = (const float*)d_in[1];   // targets  (2,4,64,256,256)
    const float* mask = (const float*)d_in[2];   // masks    (2,1,64,256,256)
    float* out = (float*)d_out;

    dim3 grid(NHX, 62, 2);
    vort_kernel<<<grid, 256>>>(pred, trgt, mask, out);
}